// round 1
// baseline (speedup 1.0000x reference)
#include <cuda_runtime.h>
#include <cstdint>

// ---------------------------------------------------------------------------
// NonLocalRGBIR: two non-local attention branches (rgb, ir) with a shared
// geometry-prior additive bias, fused flash-style softmax-attention, BN(train),
// residual add. All fp32.
//
// Shapes: B=8, C=64, IC=32, H=W=80 -> N=6400; Hp=Wp=40 -> M=1600;
//         GH=3200, GC=N=6400.
// ---------------------------------------------------------------------------

#define BQ   8
#define CC   64
#define ICH  32
#define NN   6400
#define MM   1600
#define GHH  3200
#define KDIM 3200

// ---- scratch (static device globals; no allocation) ----
__device__ float g_h[GHH * MM];                       // 20.5 MB hidden (gh, m)
__device__ float g_bias[(size_t)NN * MM];             // 41 MB bias (n, m)
__device__ float g_pool[2 * BQ * CC * MM];            // pooled (p,b,c,m)
__device__ float g_theta[(size_t)2 * BQ * ICH * NN];  // theta (p,b,ic,n)
__device__ float g_phi[2 * BQ * ICH * MM];            // phi (p,b,ic,m)
__device__ float g_gm[2 * BQ * ICH * MM];             // g   (p,b,ic,m)
__device__ float g_aout[(size_t)2 * BQ * ICH * NN];   // attention out (p,b,ic,n)
__device__ float g_z[(size_t)2 * BQ * CC * NN];       // W-proj out (p,b,c,n)
__device__ float g_stats[2 * CC * 2];                 // mean, rstd per (p,c)

// ---------------------------------------------------------------------------
// K1: geometry hidden  h[gh][m] = relu(w1[gh,0]*p0[m] + w1[gh,1]*p1[m] + b1[gh])
// ---------------------------------------------------------------------------
__global__ void k_hidden(const float* __restrict__ pos,
                         const float* __restrict__ w1,
                         const float* __restrict__ b1) {
    int idx = blockIdx.x * blockDim.x + threadIdx.x;
    if (idx >= GHH * MM) return;
    int gh = idx / MM, m = idx - gh * MM;
    float v = fmaf(w1[gh * 2], pos[m], fmaf(w1[gh * 2 + 1], pos[MM + m], b1[gh]));
    g_h[idx] = fmaxf(v, 0.0f);
}

// ---------------------------------------------------------------------------
// K2: geometry bias GEMM  bias(6400x1600) = w2(6400x3200) @ h(3200x1600)
//     (gp_b2 omitted: constant per softmax row -> cancels exactly)
//     128x64 tile, BK=16, 256 threads, 8x4 per-thread microtile.
// ---------------------------------------------------------------------------
__global__ void k_geom_gemm(const float* __restrict__ A) {
    __shared__ __align__(16) float As[16][128];
    __shared__ __align__(16) float Bs[16][64];
    const float* Bm = g_h;
    float* Cm = g_bias;
    int tid = threadIdx.x;
    int n0 = blockIdx.x * 64;    // column tile (m of bias)
    int m0 = blockIdx.y * 128;   // row tile (n of bias)
    int tx = tid & 15, ty = tid >> 4;
    float acc[8][4];
#pragma unroll
    for (int i = 0; i < 8; i++)
#pragma unroll
        for (int j = 0; j < 4; j++) acc[i][j] = 0.0f;

    for (int k0 = 0; k0 < KDIM; k0 += 16) {
#pragma unroll
        for (int l = 0; l < 2; l++) {
            int i = tid + l * 256;
            int row = i >> 2, c = i & 3;
            float4 v = *(const float4*)&A[(size_t)(m0 + row) * KDIM + k0 + c * 4];
            As[c * 4 + 0][row] = v.x;
            As[c * 4 + 1][row] = v.y;
            As[c * 4 + 2][row] = v.z;
            As[c * 4 + 3][row] = v.w;
        }
        {
            int r = tid >> 4, c4 = tid & 15;
            float4 v = *(const float4*)&Bm[(size_t)(k0 + r) * MM + n0 + c4 * 4];
            *(float4*)&Bs[r][c4 * 4] = v;
        }
        __syncthreads();
#pragma unroll
        for (int k = 0; k < 16; k++) {
            float4 a0 = *(float4*)&As[k][ty * 8];
            float4 a1 = *(float4*)&As[k][ty * 8 + 4];
            float4 bv = *(float4*)&Bs[k][tx * 4];
            float a[8] = {a0.x, a0.y, a0.z, a0.w, a1.x, a1.y, a1.z, a1.w};
            float b[4] = {bv.x, bv.y, bv.z, bv.w};
#pragma unroll
            for (int i = 0; i < 8; i++)
#pragma unroll
                for (int j = 0; j < 4; j++) acc[i][j] = fmaf(a[i], b[j], acc[i][j]);
        }
        __syncthreads();
    }
#pragma unroll
    for (int i = 0; i < 8; i++) {
        int row = m0 + ty * 8 + i;
        float4 v = make_float4(acc[i][0], acc[i][1], acc[i][2], acc[i][3]);
        *(float4*)&Cm[(size_t)row * MM + n0 + tx * 4] = v;
    }
}

// ---------------------------------------------------------------------------
// K3: 2x2 maxpool -> g_pool[p][b][c][mp]
// ---------------------------------------------------------------------------
__global__ void k_pool(const float* __restrict__ rgb, const float* __restrict__ ir) {
    int idx = blockIdx.x * blockDim.x + threadIdx.x;
    if (idx >= 2 * BQ * CC * MM) return;
    int mp = idx % MM;
    int c = (idx / MM) % CC;
    int b = (idx / (MM * CC)) % BQ;
    int p = idx / (MM * CC * BQ);
    const float* x = (p ? ir : rgb) + ((size_t)b * CC + c) * NN;
    int hp = mp / 40, wp = mp - hp * 40;
    const float* r0 = x + (2 * hp) * 80 + 2 * wp;
    g_pool[idx] = fmaxf(fmaxf(r0[0], r0[1]), fmaxf(r0[80], r0[81]));
}

// ---------------------------------------------------------------------------
// K4: theta projection: theta[p][b][ic][n] = theta_w @ x + theta_b
//     grid (50, 8, 2), tile of 128 n's.
// ---------------------------------------------------------------------------
__global__ void k_theta(const float* __restrict__ rgb, const float* __restrict__ ir,
                        const float* __restrict__ twr, const float* __restrict__ tbr,
                        const float* __restrict__ twi, const float* __restrict__ tbi) {
    __shared__ float xs[CC][128];
    __shared__ float ws[ICH * CC];
    int p = blockIdx.z, b = blockIdx.y, n0 = blockIdx.x * 128;
    const float* x = (p ? ir : rgb) + (size_t)b * CC * NN;
    const float* w = p ? twi : twr;
    const float* bb = p ? tbi : tbr;
    int tid = threadIdx.x;
    for (int i = tid; i < ICH * CC; i += 256) ws[i] = w[i];
    for (int i = tid; i < CC * 128; i += 256) {
        int c = i >> 7, j = i & 127;
        xs[c][j] = x[(size_t)c * NN + n0 + j];
    }
    __syncthreads();
    int n = tid & 127, icq = tid >> 7;  // icq in {0,1}
    float xv[CC];
#pragma unroll
    for (int c = 0; c < CC; c++) xv[c] = xs[c][n];
    for (int t = 0; t < 16; t++) {
        int ic = icq * 16 + t;
        float acc = bb[ic];
#pragma unroll
        for (int c = 0; c < CC; c++) acc = fmaf(ws[ic * CC + c], xv[c], acc);
        g_theta[((size_t)(p * BQ + b) * ICH + ic) * NN + n0 + n] = acc;
    }
}

// ---------------------------------------------------------------------------
// K5: phi & g projections from pooled. grid (10, 8, 2), tile of 160 m's.
// ---------------------------------------------------------------------------
__global__ void k_phig(const float* __restrict__ pwr, const float* __restrict__ pbr,
                       const float* __restrict__ gwr, const float* __restrict__ gbr,
                       const float* __restrict__ pwi, const float* __restrict__ pbi,
                       const float* __restrict__ gwi, const float* __restrict__ gbi) {
    __shared__ float ps[CC][160];
    int p = blockIdx.z, b = blockIdx.y, m0 = blockIdx.x * 160;
    int pb = p * BQ + b;
    int tid = threadIdx.x;
    for (int i = tid; i < CC * 160; i += 256) {
        int c = i / 160, j = i - c * 160;
        ps[c][j] = g_pool[((size_t)pb * CC + c) * MM + m0 + j];
    }
    __syncthreads();
    const float* pw = p ? pwi : pwr;
    const float* pbv = p ? pbi : pbr;
    const float* gw = p ? gwi : gwr;
    const float* gbv = p ? gbi : gbr;
    for (int o = tid; o < 2 * ICH * 160; o += 256) {
        int sel = o / (ICH * 160);
        int oo = o - sel * ICH * 160;
        int ic = oo / 160, m = oo - ic * 160;
        const float* w = sel ? gw : pw;
        float acc = sel ? gbv[ic] : pbv[ic];
#pragma unroll
        for (int c = 0; c < CC; c++) acc = fmaf(w[ic * CC + c], ps[c][m], acc);
        float* dst = sel ? g_gm : g_phi;
        dst[((size_t)pb * ICH + ic) * MM + m0 + m] = acc;
    }
}

// ---------------------------------------------------------------------------
// K6: fused attention. CTA = (b, ntile=64, p). grid (8, 100, 2).
//   scores = theta^T phi + bias; softmax over m WITHOUT max (|s| small, exact
//   math equal to reference); unnormalized O accumulation, divide at end.
// ---------------------------------------------------------------------------
__global__ void k_attn() {
    __shared__ __align__(16) float th_s[ICH][64];
    __shared__ __align__(16) float ph_s[ICH][64];
    __shared__ __align__(16) float gg_s[ICH][64];
    __shared__ __align__(16) float P_s[64][68];
    __shared__ float l_s[64];

    int tid = threadIdx.x;
    int b = blockIdx.x, n0 = blockIdx.y * 64, p = blockIdx.z;
    int pb = p * BQ + b;
    const float* thb = g_theta + (size_t)pb * ICH * NN;
    const float* phb = g_phi + (size_t)pb * ICH * MM;
    const float* ggb = g_gm + (size_t)pb * ICH * MM;

    for (int i = tid; i < ICH * 64; i += 256) {
        int ic = i >> 6, j = i & 63;
        th_s[ic][j] = thb[(size_t)ic * NN + n0 + j];
    }
    if (tid < 64) l_s[tid] = 0.0f;

    int tx = tid & 15, ty = tid >> 4;   // mapping A: 4n x 4m per thread
    int lane = tid & 31, wrp = tid >> 5; // mapping B: rows lane/lane+32, ic=wrp*4..+3
    float O[2][4];
#pragma unroll
    for (int r = 0; r < 2; r++)
#pragma unroll
        for (int k = 0; k < 4; k++) O[r][k] = 0.0f;

    for (int ch = 0; ch < 25; ch++) {
        int m0 = ch * 64;
        __syncthreads();
        for (int i = tid; i < ICH * 64; i += 256) {
            int ic = i >> 6, j = i & 63;
            ph_s[ic][j] = phb[(size_t)ic * MM + m0 + j];
            gg_s[ic][j] = ggb[(size_t)ic * MM + m0 + j];
        }
        __syncthreads();

        // ---- mapping A: S = theta^T phi + bias, P = exp(S), row sums ----
        float s[4][4];
#pragma unroll
        for (int i = 0; i < 4; i++) {
            float4 bv = *(const float4*)&g_bias[(size_t)(n0 + ty * 4 + i) * MM + m0 + tx * 4];
            s[i][0] = bv.x; s[i][1] = bv.y; s[i][2] = bv.z; s[i][3] = bv.w;
        }
#pragma unroll
        for (int ic = 0; ic < ICH; ic++) {
            float4 av = *(float4*)&th_s[ic][ty * 4];
            float4 pv = *(float4*)&ph_s[ic][tx * 4];
            float a[4] = {av.x, av.y, av.z, av.w};
            float q[4] = {pv.x, pv.y, pv.z, pv.w};
#pragma unroll
            for (int i = 0; i < 4; i++)
#pragma unroll
                for (int j = 0; j < 4; j++) s[i][j] = fmaf(a[i], q[j], s[i][j]);
        }
#pragma unroll
        for (int i = 0; i < 4; i++) {
            float e0 = __expf(s[i][0]), e1 = __expf(s[i][1]);
            float e2 = __expf(s[i][2]), e3 = __expf(s[i][3]);
            *(float4*)&P_s[ty * 4 + i][tx * 4] = make_float4(e0, e1, e2, e3);
            float rs = (e0 + e1) + (e2 + e3);
#pragma unroll
            for (int o = 8; o >= 1; o >>= 1) rs += __shfl_xor_sync(0xffffffffu, rs, o);
            if (tx == 0) l_s[ty * 4 + i] += rs;
        }
        __syncthreads();

        // ---- mapping B: O[n][ic] += P @ g^T ----
#pragma unroll
        for (int mmv = 0; mmv < 16; mmv++) {
            float4 p0 = *(float4*)&P_s[lane][mmv * 4];
            float4 p1 = *(float4*)&P_s[lane + 32][mmv * 4];
#pragma unroll
            for (int k = 0; k < 4; k++) {
                float4 gv = *(float4*)&gg_s[wrp * 4 + k][mmv * 4];
                O[0][k] += p0.x * gv.x + p0.y * gv.y + p0.z * gv.z + p0.w * gv.w;
                O[1][k] += p1.x * gv.x + p1.y * gv.y + p1.z * gv.z + p1.w * gv.w;
            }
        }
    }
    __syncthreads();
    float inv0 = 1.0f / l_s[lane];
    float inv1 = 1.0f / l_s[lane + 32];
#pragma unroll
    for (int k = 0; k < 4; k++) {
        int ic = wrp * 4 + k;
        size_t base = ((size_t)pb * ICH + ic) * NN + n0;
        g_aout[base + lane] = O[0][k] * inv0;
        g_aout[base + 32 + lane] = O[1][k] * inv1;
    }
}

// ---------------------------------------------------------------------------
// K7: W projection  z[p][b][c][n] = W_w @ aout + W_b.  grid (25, 8, 2).
// ---------------------------------------------------------------------------
__global__ void k_zproj(const float* __restrict__ Wr, const float* __restrict__ Br,
                        const float* __restrict__ Wi, const float* __restrict__ Bi) {
    __shared__ float as_[ICH][256];
    __shared__ float ws[CC * ICH];
    __shared__ float wb[CC];
    int p = blockIdx.z, b = blockIdx.y, n0 = blockIdx.x * 256;
    int pb = p * BQ + b;
    const float* W = p ? Wi : Wr;
    const float* Bb = p ? Bi : Br;
    int tid = threadIdx.x;
    for (int i = tid; i < CC * ICH; i += 256) ws[i] = W[i];
    if (tid < CC) wb[tid] = Bb[tid];
    for (int i = tid; i < ICH * 256; i += 256) {
        int ic = i >> 8, j = i & 255;
        as_[ic][j] = g_aout[((size_t)pb * ICH + ic) * NN + n0 + j];
    }
    __syncthreads();
    int n = tid;
    float a[ICH];
#pragma unroll
    for (int ic = 0; ic < ICH; ic++) a[ic] = as_[ic][n];
    for (int co = 0; co < CC; co++) {
        float acc = wb[co];
#pragma unroll
        for (int ic = 0; ic < ICH; ic++) acc = fmaf(ws[co * ICH + ic], a[ic], acc);
        g_z[((size_t)pb * CC + co) * NN + n0 + n] = acc;
    }
}

// ---------------------------------------------------------------------------
// K8: BN stats (biased variance over b,n), deterministic 2-pass per (p,c).
// ---------------------------------------------------------------------------
__global__ void k_bnstats() {
    int p = blockIdx.x >> 6, c = blockIdx.x & 63;
    __shared__ float red[256];
    __shared__ float s_mean;
    int tid = threadIdx.x;
    float sum = 0.0f;
    for (int b = 0; b < BQ; b++) {
        const float* row = g_z + ((size_t)(p * BQ + b) * CC + c) * NN;
        for (int n = tid; n < NN; n += 256) sum += row[n];
    }
    red[tid] = sum;
    __syncthreads();
    for (int s = 128; s; s >>= 1) {
        if (tid < s) red[tid] += red[tid + s];
        __syncthreads();
    }
    if (tid == 0) s_mean = red[0] * (1.0f / (BQ * NN));
    __syncthreads();
    float mean = s_mean;
    float sq = 0.0f;
    for (int b = 0; b < BQ; b++) {
        const float* row = g_z + ((size_t)(p * BQ + b) * CC + c) * NN;
        for (int n = tid; n < NN; n += 256) {
            float d = row[n] - mean;
            sq = fmaf(d, d, sq);
        }
    }
    red[tid] = sq;
    __syncthreads();
    for (int s = 128; s; s >>= 1) {
        if (tid < s) red[tid] += red[tid + s];
        __syncthreads();
    }
    if (tid == 0) {
        g_stats[blockIdx.x * 2] = mean;
        g_stats[blockIdx.x * 2 + 1] = rsqrtf(red[0] * (1.0f / (BQ * NN)) + 1e-5f);
    }
}

// ---------------------------------------------------------------------------
// K9: normalize + residual, write output (rgb_out then ir_out).
// ---------------------------------------------------------------------------
__global__ void k_final(const float* __restrict__ rgb, const float* __restrict__ ir,
                        const float* __restrict__ gr, const float* __restrict__ br,
                        const float* __restrict__ gi, const float* __restrict__ bi,
                        float* __restrict__ out) {
    int idx = blockIdx.x * blockDim.x + threadIdx.x;
    if (idx >= 2 * BQ * CC * NN) return;
    int p = idx / (BQ * CC * NN);
    int rem = idx - p * (BQ * CC * NN);
    int c = (rem / NN) & 63;
    float mean = g_stats[(p * CC + c) * 2];
    float rstd = g_stats[(p * CC + c) * 2 + 1];
    const float* gam = p ? gi : gr;
    const float* bet = p ? bi : br;
    const float* x = p ? ir : rgb;
    out[idx] = fmaf(gam[c] * (g_z[idx] - mean), rstd, bet[c]) + x[rem];
}

// ---------------------------------------------------------------------------
extern "C" void kernel_launch(void* const* d_in, const int* in_sizes, int n_in,
                              void* d_out, int out_size) {
    const float* rgb = (const float*)d_in[0];
    const float* ir  = (const float*)d_in[1];
    const float* pos = (const float*)d_in[2];
    const float* gw1 = (const float*)d_in[3];
    const float* gb1 = (const float*)d_in[4];
    const float* gw2 = (const float*)d_in[5];
    // d_in[6] = gp_b2: constant per softmax row, cancels exactly -> unused.
    const float* twr = (const float*)d_in[7],  *tbr = (const float*)d_in[8];
    const float* pwr = (const float*)d_in[9],  *pbr = (const float*)d_in[10];
    const float* gwr = (const float*)d_in[11], *gbr = (const float*)d_in[12];
    const float* Wwr = (const float*)d_in[13], *Wbr = (const float*)d_in[14];
    const float* bgr = (const float*)d_in[15], *bbr = (const float*)d_in[16];
    const float* twi = (const float*)d_in[17], *tbi = (const float*)d_in[18];
    const float* pwi = (const float*)d_in[19], *pbi = (const float*)d_in[20];
    const float* gwi = (const float*)d_in[21], *gbi = (const float*)d_in[22];
    const float* Wwi = (const float*)d_in[23], *Wbi = (const float*)d_in[24];
    const float* bgi = (const float*)d_in[25], *bbi = (const float*)d_in[26];
    float* out = (float*)d_out;

    k_hidden<<<(GHH * MM + 255) / 256, 256>>>(pos, gw1, gb1);
    k_geom_gemm<<<dim3(MM / 64, NN / 128), 256>>>(gw2);
    k_pool<<<(2 * BQ * CC * MM + 255) / 256, 256>>>(rgb, ir);
    k_theta<<<dim3(NN / 128, BQ, 2), 256>>>(rgb, ir, twr, tbr, twi, tbi);
    k_phig<<<dim3(MM / 160, BQ, 2), 256>>>(pwr, pbr, gwr, gbr, pwi, pbi, gwi, gbi);
    k_attn<<<dim3(BQ, NN / 64, 2), 256>>>();
    k_zproj<<<dim3(NN / 256, BQ, 2), 256>>>(Wwr, Wbr, Wwi, Wbi);
    k_bnstats<<<2 * CC, 256>>>();
    k_final<<<(2 * BQ * CC * NN + 255) / 256, 256>>>(rgb, ir, bgr, bbr, bgi, bbi, out);
}

// round 2
// speedup vs baseline: 1.7481x; 1.7481x over previous
#include <cuda_runtime.h>
#include <cstdint>

#define BQ   8
#define CC   64
#define ICH  32
#define NN   6400
#define MM   1600
#define GHH  3200
#define KDIM 3200

// ---- scratch (static device globals; no allocation) ----
__device__ float g_h[GHH * MM];
__device__ float g_bias[(size_t)NN * MM];
__device__ float g_pool[2 * BQ * CC * MM];
__device__ float g_theta[(size_t)2 * BQ * ICH * NN];
__device__ float g_phi[2 * BQ * ICH * MM];
__device__ float g_gm[2 * BQ * ICH * MM];
__device__ float g_aout[(size_t)2 * BQ * ICH * NN];
__device__ float g_z[(size_t)2 * BQ * CC * NN];
__device__ float g_stats[2 * CC * 2];

// ---------------------------------------------------------------------------
// helpers
// ---------------------------------------------------------------------------
__device__ __forceinline__ uint32_t to_tf32(float x) {
    uint32_t r;
    asm("cvt.rna.tf32.f32 %0, %1;" : "=r"(r) : "f"(x));
    return r;
}

__device__ __forceinline__ void cp16(void* dst, const void* src) {
    uint32_t d = (uint32_t)__cvta_generic_to_shared(dst);
    asm volatile("cp.async.cg.shared.global [%0], [%1], 16;" :: "r"(d), "l"(src));
}
#define CP_COMMIT asm volatile("cp.async.commit_group;")
#define CP_WAIT1  asm volatile("cp.async.wait_group 1;")
#define CP_WAIT0  asm volatile("cp.async.wait_group 0;")

// FMA-only exp: exp(x) = 2^(x*log2e), round-to-nearest split, deg-6 poly.
__device__ __forceinline__ float fexp(float x) {
    float t = x * 1.4426950408889634f;
    float r = __fadd_rn(t, 12582912.0f);          // round-to-nearest int
    int ei = __float_as_int(r) - 0x4B400000;      // the integer part
    float fi = __fsub_rn(r, 12582912.0f);
    float f = __fsub_rn(t, fi);                   // frac in [-0.5, 0.5]
    float p = 1.5403530e-4f;
    p = fmaf(p, f, 1.3333558e-3f);
    p = fmaf(p, f, 9.6181291e-3f);
    p = fmaf(p, f, 5.5504109e-2f);
    p = fmaf(p, f, 2.4022651e-1f);
    p = fmaf(p, f, 6.9314718e-1f);
    p = fmaf(p, f, 1.0f);
    return __int_as_float(__float_as_int(p) + (ei << 23));
}

// ---------------------------------------------------------------------------
// K1: geometry hidden
// ---------------------------------------------------------------------------
__global__ void k_hidden(const float* __restrict__ pos,
                         const float* __restrict__ w1,
                         const float* __restrict__ b1) {
    int idx = blockIdx.x * blockDim.x + threadIdx.x;
    if (idx >= GHH * MM) return;
    int gh = idx / MM, m = idx - gh * MM;
    float v = fmaf(w1[gh * 2], pos[m], fmaf(w1[gh * 2 + 1], pos[MM + m], b1[gh]));
    g_h[idx] = fmaxf(v, 0.0f);
}

// ---------------------------------------------------------------------------
// K2: geometry bias GEMM via tf32 mma.sync. C(6400x1600)=A(6400x3200)B(3200x1600)
//     CTA tile 128x128, BK=16, 8 warps (warp tile 32x64), cp.async double-buffer.
// ---------------------------------------------------------------------------
__global__ void __launch_bounds__(256) k_geom_tf32(const float* __restrict__ A) {
    __shared__ float As[2][128][28];   // [row][k], stride 28 (conflict-free, 16B-aligned)
    __shared__ float Bs[2][16][136];   // [k][col], stride 136

    const float* Bm = g_h;
    int tid = threadIdx.x, warp = tid >> 5, lane = tid & 31;
    int m0 = blockIdx.y * 128, n0 = blockIdx.x * 128;
    int wr = warp >> 1, wc = warp & 1;        // warp grid 4x2 (rows x cols)
    int g = lane >> 2, j = lane & 3;

    float acc[2][8][4];
#pragma unroll
    for (int i = 0; i < 2; i++)
#pragma unroll
        for (int t = 0; t < 8; t++)
#pragma unroll
            for (int v = 0; v < 4; v++) acc[i][t][v] = 0.0f;

    // prefetch stage 0
#pragma unroll
    for (int l = 0; l < 2; l++) {
        int id = tid + l * 256;
        int row = id >> 2, kq = id & 3;
        cp16(&As[0][row][kq * 4], &A[(size_t)(m0 + row) * KDIM + kq * 4]);
    }
#pragma unroll
    for (int l = 0; l < 2; l++) {
        int id = tid + l * 256;
        int k = id >> 5, cq = id & 31;
        int col = n0 + cq * 4; if (col > 1596) col = 1596;
        cp16(&Bs[0][k][cq * 4], &Bm[(size_t)k * MM + col]);
    }
    CP_COMMIT;

    const int NIT = KDIM / 16;  // 200
    for (int it = 0; it < NIT; it++) {
        int s = it & 1;
        if (it + 1 < NIT) {
            int k0 = (it + 1) * 16, sn = s ^ 1;
#pragma unroll
            for (int l = 0; l < 2; l++) {
                int id = tid + l * 256;
                int row = id >> 2, kq = id & 3;
                cp16(&As[sn][row][kq * 4], &A[(size_t)(m0 + row) * KDIM + k0 + kq * 4]);
            }
#pragma unroll
            for (int l = 0; l < 2; l++) {
                int id = tid + l * 256;
                int k = id >> 5, cq = id & 31;
                int col = n0 + cq * 4; if (col > 1596) col = 1596;
                cp16(&Bs[sn][k][cq * 4], &Bm[(size_t)(k0 + k) * MM + col]);
            }
            CP_COMMIT;
            CP_WAIT1;
        } else {
            CP_WAIT0;
        }
        __syncthreads();

#pragma unroll
        for (int kk = 0; kk < 2; kk++) {
            uint32_t af[2][4];
#pragma unroll
            for (int i = 0; i < 2; i++) {
                int r = wr * 32 + i * 16 + g;
                af[i][0] = to_tf32(As[s][r][kk * 8 + j]);
                af[i][1] = to_tf32(As[s][r + 8][kk * 8 + j]);
                af[i][2] = to_tf32(As[s][r][kk * 8 + j + 4]);
                af[i][3] = to_tf32(As[s][r + 8][kk * 8 + j + 4]);
            }
#pragma unroll
            for (int t = 0; t < 8; t++) {
                int c = wc * 64 + t * 8 + g;
                uint32_t b0 = to_tf32(Bs[s][kk * 8 + j][c]);
                uint32_t b1 = to_tf32(Bs[s][kk * 8 + j + 4][c]);
#pragma unroll
                for (int i = 0; i < 2; i++) {
                    asm volatile(
                        "mma.sync.aligned.m16n8k8.row.col.f32.tf32.tf32.f32 "
                        "{%0,%1,%2,%3}, {%4,%5,%6,%7}, {%8,%9}, {%0,%1,%2,%3};"
                        : "+f"(acc[i][t][0]), "+f"(acc[i][t][1]),
                          "+f"(acc[i][t][2]), "+f"(acc[i][t][3])
                        : "r"(af[i][0]), "r"(af[i][1]), "r"(af[i][2]), "r"(af[i][3]),
                          "r"(b0), "r"(b1));
                }
            }
        }
        __syncthreads();
    }

#pragma unroll
    for (int i = 0; i < 2; i++) {
        int r = m0 + wr * 32 + i * 16 + g;
#pragma unroll
        for (int t = 0; t < 8; t++) {
            int c = n0 + wc * 64 + t * 8 + 2 * j;
            if (c < MM) {
                float2 v0 = make_float2(acc[i][t][0], acc[i][t][1]);
                float2 v1 = make_float2(acc[i][t][2], acc[i][t][3]);
                *(float2*)&g_bias[(size_t)r * MM + c] = v0;
                *(float2*)&g_bias[(size_t)(r + 8) * MM + c] = v1;
            }
        }
    }
}

// ---------------------------------------------------------------------------
// K3: 2x2 maxpool
// ---------------------------------------------------------------------------
__global__ void k_pool(const float* __restrict__ rgb, const float* __restrict__ ir) {
    int idx = blockIdx.x * blockDim.x + threadIdx.x;
    if (idx >= 2 * BQ * CC * MM) return;
    int mp = idx % MM;
    int c = (idx / MM) % CC;
    int b = (idx / (MM * CC)) % BQ;
    int p = idx / (MM * CC * BQ);
    const float* x = (p ? ir : rgb) + ((size_t)b * CC + c) * NN;
    int hp = mp / 40, wp = mp - hp * 40;
    const float* r0 = x + (2 * hp) * 80 + 2 * wp;
    g_pool[idx] = fmaxf(fmaxf(r0[0], r0[1]), fmaxf(r0[80], r0[81]));
}

// ---------------------------------------------------------------------------
// K4: theta projection
// ---------------------------------------------------------------------------
__global__ void k_theta(const float* __restrict__ rgb, const float* __restrict__ ir,
                        const float* __restrict__ twr, const float* __restrict__ tbr,
                        const float* __restrict__ twi, const float* __restrict__ tbi) {
    __shared__ float xs[CC][128];
    __shared__ float ws[ICH * CC];
    int p = blockIdx.z, b = blockIdx.y, n0 = blockIdx.x * 128;
    const float* x = (p ? ir : rgb) + (size_t)b * CC * NN;
    const float* w = p ? twi : twr;
    const float* bb = p ? tbi : tbr;
    int tid = threadIdx.x;
    for (int i = tid; i < ICH * CC; i += 256) ws[i] = w[i];
    for (int i = tid; i < CC * 128; i += 256) {
        int c = i >> 7, j = i & 127;
        xs[c][j] = x[(size_t)c * NN + n0 + j];
    }
    __syncthreads();
    int n = tid & 127, icq = tid >> 7;
    float xv[CC];
#pragma unroll
    for (int c = 0; c < CC; c++) xv[c] = xs[c][n];
    for (int t = 0; t < 16; t++) {
        int ic = icq * 16 + t;
        float acc = bb[ic];
#pragma unroll
        for (int c = 0; c < CC; c++) acc = fmaf(ws[ic * CC + c], xv[c], acc);
        g_theta[((size_t)(p * BQ + b) * ICH + ic) * NN + n0 + n] = acc;
    }
}

// ---------------------------------------------------------------------------
// K5: phi & g projections
// ---------------------------------------------------------------------------
__global__ void k_phig(const float* __restrict__ pwr, const float* __restrict__ pbr,
                       const float* __restrict__ gwr, const float* __restrict__ gbr,
                       const float* __restrict__ pwi, const float* __restrict__ pbi,
                       const float* __restrict__ gwi, const float* __restrict__ gbi) {
    __shared__ float ps[CC][160];
    int p = blockIdx.z, b = blockIdx.y, m0 = blockIdx.x * 160;
    int pb = p * BQ + b;
    int tid = threadIdx.x;
    for (int i = tid; i < CC * 160; i += 256) {
        int c = i / 160, j = i - c * 160;
        ps[c][j] = g_pool[((size_t)pb * CC + c) * MM + m0 + j];
    }
    __syncthreads();
    const float* pw = p ? pwi : pwr;
    const float* pbv = p ? pbi : pbr;
    const float* gw = p ? gwi : gwr;
    const float* gbv = p ? gbi : gbr;
    for (int o = tid; o < 2 * ICH * 160; o += 256) {
        int sel = o / (ICH * 160);
        int oo = o - sel * ICH * 160;
        int ic = oo / 160, m = oo - ic * 160;
        const float* w = sel ? gw : pw;
        float acc = sel ? gbv[ic] : pbv[ic];
#pragma unroll
        for (int c = 0; c < CC; c++) acc = fmaf(w[ic * CC + c], ps[c][m], acc);
        float* dst = sel ? g_gm : g_phi;
        dst[((size_t)pb * ICH + ic) * MM + m0 + m] = acc;
    }
}

// ---------------------------------------------------------------------------
// K6: fused attention. CTA tile: 128 n-rows, m-chunks of 64 (25 chunks).
//     Scores: 16x16 thread grid, 8x4 microtile. exp via FMA-only poly.
//     P buffer: [n][64] with XOR swizzle key (n>>3)&7 on 16B granules.
//     AV: 4 quarters over m, each 64 threads with 8-row x 8-ic microtile;
//     partial O reduced through smem at the end.
// ---------------------------------------------------------------------------
#define ATTN_SMEM_FLOATS (32*132 + 32*68 + 32*68 + 128*64 + 128)
#define ATTN_SMEM_BYTES  (ATTN_SMEM_FLOATS * 4)

__global__ void __launch_bounds__(256, 2) k_attn() {
    extern __shared__ float sm[];
    float* th   = sm;            // 32 x 132
    float* ph   = sm + 4224;     // 32 x 68
    float* gg   = sm + 6400;     // 32 x 68
    float* P    = sm + 8576;     // 128 x 64 (swizzled)
    float* lrow = sm + 16768;    // 128

    int tid = threadIdx.x;
    int b = blockIdx.x, n0 = blockIdx.y * 128, p = blockIdx.z;
    int pb = p * BQ + b;
    const float* thb = g_theta + (size_t)pb * ICH * NN + n0;
    const float* phb = g_phi + (size_t)pb * ICH * MM;
    const float* ggb = g_gm + (size_t)pb * ICH * MM;

    // load theta tile (32 ic x 128 n)
    for (int i = tid; i < 1024; i += 256) {
        int ic = i >> 5, jq = i & 31;
        *(float4*)&th[ic * 132 + jq * 4] = *(const float4*)&thb[(size_t)ic * NN + jq * 4];
    }
    if (tid < 128) lrow[tid] = 0.0f;

    int ty = tid >> 4, tx = tid & 15;          // scores mapping
    int q = tid >> 6, t = tid & 63;            // AV mapping
    int rg = t & 15, icg = t >> 4;

    float O[8][8];
#pragma unroll
    for (int i = 0; i < 8; i++)
#pragma unroll
        for (int k = 0; k < 8; k++) O[i][k] = 0.0f;

    for (int ch = 0; ch < 25; ch++) {
        int m0 = ch * 64;
        __syncthreads();
        // load phi & g chunk (each 32 ic x 64 m)
        for (int i = tid; i < 1024; i += 256) {
            int sel = i >> 9, ii = i & 511;
            int ic = ii >> 4, jq = ii & 15;
            const float* srcb = sel ? ggb : phb;
            float* dst = sel ? gg : ph;
            *(float4*)&dst[ic * 68 + jq * 4] =
                *(const float4*)&srcb[(size_t)ic * MM + m0 + jq * 4];
        }
        __syncthreads();

        // ---- scores: s[8 rows][4 cols] = theta^T phi + bias ----
        float s[8][4];
#pragma unroll
        for (int i = 0; i < 8; i++) {
            float4 bv = *(const float4*)&g_bias[(size_t)(n0 + ty * 8 + i) * MM + m0 + tx * 4];
            s[i][0] = bv.x; s[i][1] = bv.y; s[i][2] = bv.z; s[i][3] = bv.w;
        }
#pragma unroll
        for (int ic = 0; ic < ICH; ic++) {
            float4 a0 = *(float4*)&th[ic * 132 + ty * 8];
            float4 a1 = *(float4*)&th[ic * 132 + ty * 8 + 4];
            float4 bv = *(float4*)&ph[ic * 68 + tx * 4];
            float av[8] = {a0.x, a0.y, a0.z, a0.w, a1.x, a1.y, a1.z, a1.w};
            float bb[4] = {bv.x, bv.y, bv.z, bv.w};
#pragma unroll
            for (int i = 0; i < 8; i++)
#pragma unroll
                for (int jj = 0; jj < 4; jj++) s[i][jj] = fmaf(av[i], bb[jj], s[i][jj]);
        }
        // exp + row sums + swizzled store to P
        int swz = (tx ^ (ty & 7)) << 2;
#pragma unroll
        for (int i = 0; i < 8; i++) {
            float e0 = fexp(s[i][0]), e1 = fexp(s[i][1]);
            float e2 = fexp(s[i][2]), e3 = fexp(s[i][3]);
            int n = ty * 8 + i;
            *(float4*)&P[n * 64 + swz] = make_float4(e0, e1, e2, e3);
            float rs = (e0 + e1) + (e2 + e3);
#pragma unroll
            for (int o = 8; o >= 1; o >>= 1) rs += __shfl_xor_sync(0xffffffffu, rs, o);
            if (tx == 0) lrow[n] += rs;
        }
        __syncthreads();

        // ---- AV: quarter q handles m-local [q*16, q*16+16) ----
#pragma unroll
        for (int mm = 0; mm < 4; mm++) {
            int mloc = q * 16 + mm * 4;
            float4 gv[8];
#pragma unroll
            for (int k = 0; k < 8; k++)
                gv[k] = *(float4*)&gg[(icg * 8 + k) * 68 + mloc];
            int pg = (((mloc >> 2) ^ (rg & 7)) << 2);
#pragma unroll
            for (int i = 0; i < 8; i++) {
                int r = rg * 8 + i;
                float4 pv = *(float4*)&P[r * 64 + pg];
#pragma unroll
                for (int k = 0; k < 8; k++) {
                    O[i][k] = fmaf(pv.x, gv[k].x, O[i][k]);
                    O[i][k] = fmaf(pv.y, gv[k].y, O[i][k]);
                    O[i][k] = fmaf(pv.z, gv[k].z, O[i][k]);
                    O[i][k] = fmaf(pv.w, gv[k].w, O[i][k]);
                }
            }
        }
    }

    // ---- reduce partial O across quarters (scratch = P area, 8192 floats) ----
    __syncthreads();
    float* scr = P;
    if (q == 1) {
#pragma unroll
        for (int i = 0; i < 8; i++)
#pragma unroll
            for (int k = 0; k < 8; k++) scr[(i * 8 + k) * 64 + t] = O[i][k];
    }
    if (q == 3) {
#pragma unroll
        for (int i = 0; i < 8; i++)
#pragma unroll
            for (int k = 0; k < 8; k++) scr[4096 + (i * 8 + k) * 64 + t] = O[i][k];
    }
    __syncthreads();
    if (q == 0) {
#pragma unroll
        for (int i = 0; i < 8; i++)
#pragma unroll
            for (int k = 0; k < 8; k++) O[i][k] += scr[(i * 8 + k) * 64 + t];
    }
    if (q == 2) {
#pragma unroll
        for (int i = 0; i < 8; i++)
#pragma unroll
            for (int k = 0; k < 8; k++) O[i][k] += scr[4096 + (i * 8 + k) * 64 + t];
    }
    __syncthreads();
    if (q == 2) {
#pragma unroll
        for (int i = 0; i < 8; i++)
#pragma unroll
            for (int k = 0; k < 8; k++) scr[(i * 8 + k) * 64 + t] = O[i][k];
    }
    __syncthreads();
    if (q == 0) {
        float inv[8];
#pragma unroll
        for (int i = 0; i < 8; i++) {
#pragma unroll
            for (int k = 0; k < 8; k++) O[i][k] += scr[(i * 8 + k) * 64 + t];
            inv[i] = 1.0f / lrow[rg * 8 + i];
        }
#pragma unroll
        for (int k = 0; k < 8; k++) {
            int ic = icg * 8 + k;
            size_t base = ((size_t)pb * ICH + ic) * NN + n0 + rg * 8;
            *(float4*)&g_aout[base] = make_float4(O[0][k] * inv[0], O[1][k] * inv[1],
                                                  O[2][k] * inv[2], O[3][k] * inv[3]);
            *(float4*)&g_aout[base + 4] = make_float4(O[4][k] * inv[4], O[5][k] * inv[5],
                                                      O[6][k] * inv[6], O[7][k] * inv[7]);
        }
    }
}

// ---------------------------------------------------------------------------
// K7: W projection
// ---------------------------------------------------------------------------
__global__ void k_zproj(const float* __restrict__ Wr, const float* __restrict__ Br,
                        const float* __restrict__ Wi, const float* __restrict__ Bi) {
    __shared__ float as_[ICH][256];
    __shared__ float ws[CC * ICH];
    __shared__ float wb[CC];
    int p = blockIdx.z, b = blockIdx.y, n0 = blockIdx.x * 256;
    int pb = p * BQ + b;
    const float* W = p ? Wi : Wr;
    const float* Bb = p ? Bi : Br;
    int tid = threadIdx.x;
    for (int i = tid; i < CC * ICH; i += 256) ws[i] = W[i];
    if (tid < CC) wb[tid] = Bb[tid];
    for (int i = tid; i < ICH * 256; i += 256) {
        int ic = i >> 8, j = i & 255;
        as_[ic][j] = g_aout[((size_t)pb * ICH + ic) * NN + n0 + j];
    }
    __syncthreads();
    int n = tid;
    float a[ICH];
#pragma unroll
    for (int ic = 0; ic < ICH; ic++) a[ic] = as_[ic][n];
    for (int co = 0; co < CC; co++) {
        float acc = wb[co];
#pragma unroll
        for (int ic = 0; ic < ICH; ic++) acc = fmaf(ws[co * ICH + ic], a[ic], acc);
        g_z[((size_t)pb * CC + co) * NN + n0 + n] = acc;
    }
}

// ---------------------------------------------------------------------------
// K8: BN stats
// ---------------------------------------------------------------------------
__global__ void k_bnstats() {
    int p = blockIdx.x >> 6, c = blockIdx.x & 63;
    __shared__ float red[256];
    __shared__ float s_mean;
    int tid = threadIdx.x;
    float sum = 0.0f;
    for (int b = 0; b < BQ; b++) {
        const float* row = g_z + ((size_t)(p * BQ + b) * CC + c) * NN;
        for (int n = tid; n < NN; n += 256) sum += row[n];
    }
    red[tid] = sum;
    __syncthreads();
    for (int s = 128; s; s >>= 1) {
        if (tid < s) red[tid] += red[tid + s];
        __syncthreads();
    }
    if (tid == 0) s_mean = red[0] * (1.0f / (BQ * NN));
    __syncthreads();
    float mean = s_mean;
    float sq = 0.0f;
    for (int b = 0; b < BQ; b++) {
        const float* row = g_z + ((size_t)(p * BQ + b) * CC + c) * NN;
        for (int n = tid; n < NN; n += 256) {
            float d = row[n] - mean;
            sq = fmaf(d, d, sq);
        }
    }
    red[tid] = sq;
    __syncthreads();
    for (int s = 128; s; s >>= 1) {
        if (tid < s) red[tid] += red[tid + s];
        __syncthreads();
    }
    if (tid == 0) {
        g_stats[blockIdx.x * 2] = mean;
        g_stats[blockIdx.x * 2 + 1] = rsqrtf(red[0] * (1.0f / (BQ * NN)) + 1e-5f);
    }
}

// ---------------------------------------------------------------------------
// K9: normalize + residual
// ---------------------------------------------------------------------------
__global__ void k_final(const float* __restrict__ rgb, const float* __restrict__ ir,
                        const float* __restrict__ gr, const float* __restrict__ br,
                        const float* __restrict__ gi, const float* __restrict__ bi,
                        float* __restrict__ out) {
    int idx = blockIdx.x * blockDim.x + threadIdx.x;
    if (idx >= 2 * BQ * CC * NN) return;
    int p = idx / (BQ * CC * NN);
    int rem = idx - p * (BQ * CC * NN);
    int c = (rem / NN) & 63;
    float mean = g_stats[(p * CC + c) * 2];
    float rstd = g_stats[(p * CC + c) * 2 + 1];
    const float* gam = p ? gi : gr;
    const float* bet = p ? bi : br;
    const float* x = p ? ir : rgb;
    out[idx] = fmaf(gam[c] * (g_z[idx] - mean), rstd, bet[c]) + x[rem];
}

// ---------------------------------------------------------------------------
extern "C" void kernel_launch(void* const* d_in, const int* in_sizes, int n_in,
                              void* d_out, int out_size) {
    const float* rgb = (const float*)d_in[0];
    const float* ir  = (const float*)d_in[1];
    const float* pos = (const float*)d_in[2];
    const float* gw1 = (const float*)d_in[3];
    const float* gb1 = (const float*)d_in[4];
    const float* gw2 = (const float*)d_in[5];
    // d_in[6] = gp_b2: constant per softmax row, cancels exactly -> unused.
    const float* twr = (const float*)d_in[7],  *tbr = (const float*)d_in[8];
    const float* pwr = (const float*)d_in[9],  *pbr = (const float*)d_in[10];
    const float* gwr = (const float*)d_in[11], *gbr = (const float*)d_in[12];
    const float* Wwr = (const float*)d_in[13], *Wbr = (const float*)d_in[14];
    const float* bgr = (const float*)d_in[15], *bbr = (const float*)d_in[16];
    const float* twi = (const float*)d_in[17], *tbi = (const float*)d_in[18];
    const float* pwi = (const float*)d_in[19], *pbi = (const float*)d_in[20];
    const float* gwi = (const float*)d_in[21], *gbi = (const float*)d_in[22];
    const float* Wwi = (const float*)d_in[23], *Wbi = (const float*)d_in[24];
    const float* bgi = (const float*)d_in[25], *bbi = (const float*)d_in[26];
    float* out = (float*)d_out;

    cudaFuncSetAttribute(k_attn, cudaFuncAttributeMaxDynamicSharedMemorySize,
                         ATTN_SMEM_BYTES);

    k_hidden<<<(GHH * MM + 255) / 256, 256>>>(pos, gw1, gb1);
    k_geom_tf32<<<dim3(13, NN / 128), 256>>>(gw2);
    k_pool<<<(2 * BQ * CC * MM + 255) / 256, 256>>>(rgb, ir);
    k_theta<<<dim3(NN / 128, BQ, 2), 256>>>(rgb, ir, twr, tbr, twi, tbi);
    k_phig<<<dim3(MM / 160, BQ, 2), 256>>>(pwr, pbr, gwr, gbr, pwi, pbi, gwi, gbi);
    k_attn<<<dim3(BQ, NN / 128, 2), 256, ATTN_SMEM_BYTES>>>();
    k_zproj<<<dim3(NN / 256, BQ, 2), 256>>>(Wwr, Wbr, Wwi, Wbi);
    k_bnstats<<<2 * CC, 256>>>();
    k_final<<<(2 * BQ * CC * NN + 255) / 256, 256>>>(rgb, ir, bgr, bbr, bgi, bbi, out);
}